// round 1
// baseline (speedup 1.0000x reference)
#include <cuda_runtime.h>
#include <math.h>

// ---------------- problem constants ----------------
#define BB 4
#define CC 512
#define CI 256
#define TT 16
#define HH 28
#define WW 28
#define NN 12544            // TT*HH*WW
#define TP 8
#define HP 14
#define WP 14
#define MM 1568             // TP*HP*WP
#define EPS 1e-5f

// ---------------- scratch layout (floats) ----------------
// theta : (b, n, ci)        12,845,056
// g     : (b, m, ci)         1,605,632
// phi   : (b, m, ci)         1,605,632
// f     : (b, n, m)         78,675,968   (also aliases gfull/phifull before f is computed)
// y     : (b, n, ci)        12,845,056
// wy    : (b, c, n)         25,690,112
#define OFF_THETA 0LL
#define OFF_G     12845056LL
#define OFF_PHI   14450688LL
#define OFF_F     16056320LL
#define OFF_Y     94732288LL
#define OFF_WY    107577344LL
#define SCRATCH_TOTAL 133267456LL

__device__ __align__(16) float d_scratch[SCRATCH_TOTAL];
__device__ __align__(16) float d_stats[2 * CC];

// ---------------- generic tiled SGEMM ----------------
// C(Mrows x Ncols) = A(Mrows x K, row-major, lda) * B + bias[row]
// BL == 0 : B is (K x Ncols) row-major, ldb      (NN)
// BL == 1 : B is (Ncols x K) row-major, ldb      (NT, i.e. B^T)
// EPI == 0: C[row*ldc + col]       (row-major)
// EPI == 1: C[col*ldc + row]       (transposed write)
// Mrows must be a multiple of 128; K a multiple of 8; Ncols arbitrary.
template <int BL, int EPI>
__global__ __launch_bounds__(256)
void sgemm_kernel(const float* __restrict__ A, const float* __restrict__ Bm,
                  float* __restrict__ Cm, const float* __restrict__ bias,
                  int Ncols, int K, int lda, int ldb, int ldc,
                  long long sA, long long sB, long long sC)
{
    __shared__ float As[8][128];
    __shared__ float Bs[8][128];

    const int bz = blockIdx.z;
    A  += (long long)bz * sA;
    Bm += (long long)bz * sB;
    Cm += (long long)bz * sC;

    const int n0 = blockIdx.x * 128;
    const int m0 = blockIdx.y * 128;
    const int tid = threadIdx.x;
    const int tx = tid & 15;
    const int ty = tid >> 4;

    float acc[8][8];
#pragma unroll
    for (int i = 0; i < 8; i++)
#pragma unroll
        for (int j = 0; j < 8; j++) acc[i][j] = 0.f;

    const int arow = tid >> 1;
    const int ak4  = (tid & 1) * 4;

    for (int k0 = 0; k0 < K; k0 += 8) {
        // ---- load A tile (always K-contiguous rows) ----
        float4 av = *(const float4*)(A + (long long)(m0 + arow) * lda + k0 + ak4);
        As[ak4 + 0][arow] = av.x;
        As[ak4 + 1][arow] = av.y;
        As[ak4 + 2][arow] = av.z;
        As[ak4 + 3][arow] = av.w;

        // ---- load B tile ----
        if (BL == 0) {
            const int bk = tid >> 5;
            const int bn = (tid & 31) * 4;
            const int gn = n0 + bn;
            float4 bv;
            const float* bp = Bm + (long long)(k0 + bk) * ldb + gn;
            if (gn + 3 < Ncols) {
                bv = *(const float4*)bp;
            } else {
                bv.x = (gn + 0 < Ncols) ? bp[0] : 0.f;
                bv.y = (gn + 1 < Ncols) ? bp[1] : 0.f;
                bv.z = (gn + 2 < Ncols) ? bp[2] : 0.f;
                bv.w = (gn + 3 < Ncols) ? bp[3] : 0.f;
            }
            *(float4*)&Bs[bk][bn] = bv;
        } else {
            const int bn  = tid >> 1;
            const int bk4 = (tid & 1) * 4;
            const int gn  = n0 + bn;
            float4 bv = make_float4(0.f, 0.f, 0.f, 0.f);
            if (gn < Ncols)
                bv = *(const float4*)(Bm + (long long)gn * ldb + k0 + bk4);
            Bs[bk4 + 0][bn] = bv.x;
            Bs[bk4 + 1][bn] = bv.y;
            Bs[bk4 + 2][bn] = bv.z;
            Bs[bk4 + 3][bn] = bv.w;
        }
        __syncthreads();

#pragma unroll
        for (int kk = 0; kk < 8; kk++) {
            float a[8], b[8];
            *(float4*)&a[0] = *(const float4*)&As[kk][ty * 4];
            *(float4*)&a[4] = *(const float4*)&As[kk][64 + ty * 4];
            *(float4*)&b[0] = *(const float4*)&Bs[kk][tx * 4];
            *(float4*)&b[4] = *(const float4*)&Bs[kk][64 + tx * 4];
#pragma unroll
            for (int i = 0; i < 8; i++)
#pragma unroll
                for (int j = 0; j < 8; j++)
                    acc[i][j] += a[i] * b[j];
        }
        __syncthreads();
    }

    // ---- epilogue ----
#pragma unroll
    for (int i = 0; i < 8; i++) {
        const int row = m0 + ((i < 4) ? (ty * 4 + i) : (64 + ty * 4 + i - 4));
        const float bi = bias ? bias[row] : 0.f;
#pragma unroll
        for (int j = 0; j < 8; j++) {
            const int col = n0 + ((j < 4) ? (tx * 4 + j) : (64 + tx * 4 + j - 4));
            if (col < Ncols) {
                const float v = acc[i][j] + bi;
                if (EPI == 0) Cm[(long long)row * ldc + col] = v;
                else          Cm[(long long)col * ldc + row] = v;
            }
        }
    }
}

// ---------------- 2x2x2 max pool + transpose to (b, m, ci) ----------------
__global__ void pool_kernel(const float* __restrict__ gfull,
                            const float* __restrict__ pfull,
                            float* __restrict__ gout,
                            float* __restrict__ pout)
{
    const int bc = blockIdx.x;            // b*CI + ci
    const int b  = bc / CI;
    const int ci = bc % CI;
    const int tp = blockIdx.y;
    const int tid = threadIdx.x;
    if (tid >= HP * WP) return;
    const int hp = tid / WP;
    const int wp = tid % WP;

    const float* gb = gfull + (long long)bc * NN;
    const float* pb = pfull + (long long)bc * NN;
    float gm = -1e30f, pm = -1e30f;
#pragma unroll
    for (int dt = 0; dt < 2; dt++)
#pragma unroll
        for (int dh = 0; dh < 2; dh++)
#pragma unroll
            for (int dw = 0; dw < 2; dw++) {
                const int n = (2 * tp + dt) * (HH * WW) + (2 * hp + dh) * WW + (2 * wp + dw);
                gm = fmaxf(gm, gb[n]);
                pm = fmaxf(pm, pb[n]);
            }
    const int m = (tp * HP + hp) * WP + wp;
    gout[((long long)b * MM + m) * CI + ci] = gm;
    pout[((long long)b * MM + m) * CI + ci] = pm;
}

// ---------------- row softmax over M=1568, in place ----------------
__global__ void softmax_kernel(float* __restrict__ f)
{
    const long long row = blockIdx.x;
    float* p = f + row * MM;
    const int tid = threadIdx.x;
    __shared__ float red[128];

    float mx = -1e30f;
    for (int i = tid; i < MM; i += 128) mx = fmaxf(mx, p[i]);
    red[tid] = mx;
    __syncthreads();
    for (int s = 64; s > 0; s >>= 1) {
        if (tid < s) red[tid] = fmaxf(red[tid], red[tid + s]);
        __syncthreads();
    }
    mx = red[0];
    __syncthreads();

    float sum = 0.f;
    for (int i = tid; i < MM; i += 128) {
        const float e = __expf(p[i] - mx);
        p[i] = e;
        sum += e;
    }
    red[tid] = sum;
    __syncthreads();
    for (int s = 64; s > 0; s >>= 1) {
        if (tid < s) red[tid] += red[tid + s];
        __syncthreads();
    }
    const float inv = 1.f / red[0];
    for (int i = tid; i < MM; i += 128) p[i] *= inv;
}

// ---------------- per-channel batch stats over (b, n) ----------------
__global__ void stats_kernel(const float* __restrict__ wy, float* __restrict__ stats)
{
    const int c = blockIdx.x;
    const int tid = threadIdx.x;
    float s = 0.f, ss = 0.f;
    for (int b = 0; b < BB; b++) {
        const float* p = wy + ((long long)b * CC + c) * NN;
        for (int i = tid; i < NN; i += 256) {
            const float v = p[i];
            s += v;
            ss += v * v;
        }
    }
    __shared__ float rs[256], rss[256];
    rs[tid] = s;
    rss[tid] = ss;
    __syncthreads();
    for (int st = 128; st > 0; st >>= 1) {
        if (tid < st) { rs[tid] += rs[tid + st]; rss[tid] += rss[tid + st]; }
        __syncthreads();
    }
    if (tid == 0) {
        const float cnt = (float)(BB * NN);
        const float mean = rs[0] / cnt;
        const float var = rss[0] / cnt - mean * mean;
        stats[c] = mean;
        stats[CC + c] = rsqrtf(var + EPS);
    }
}

// ---------------- BN affine + residual ----------------
__global__ void final_kernel(const float* __restrict__ wy, const float* __restrict__ x,
                             const float* __restrict__ gamma, const float* __restrict__ beta,
                             const float* __restrict__ stats, float* __restrict__ out)
{
    const long long idx = (long long)blockIdx.x * blockDim.x + threadIdx.x;
    const long long total = (long long)BB * CC * NN / 4;
    if (idx >= total) return;
    const int c = (int)((idx * 4 / NN) % CC);
    const float mean = stats[c];
    const float rstd = stats[CC + c];
    const float g = gamma[c] * rstd;
    const float bt = beta[c] - mean * g;
    const float4 wv = ((const float4*)wy)[idx];
    const float4 xv = ((const float4*)x)[idx];
    float4 o;
    o.x = wv.x * g + bt + xv.x;
    o.y = wv.y * g + bt + xv.y;
    o.z = wv.z * g + bt + xv.z;
    o.w = wv.w * g + bt + xv.w;
    ((float4*)out)[idx] = o;
}

// ---------------- launch ----------------
extern "C" void kernel_launch(void* const* d_in, const int* in_sizes, int n_in,
                              void* d_out, int out_size)
{
    const float* x       = (const float*)d_in[0];
    const float* g_w     = (const float*)d_in[1];
    const float* g_b     = (const float*)d_in[2];
    const float* theta_w = (const float*)d_in[3];
    const float* theta_b = (const float*)d_in[4];
    const float* phi_w   = (const float*)d_in[5];
    const float* phi_b   = (const float*)d_in[6];
    const float* W_w     = (const float*)d_in[7];
    const float* W_b     = (const float*)d_in[8];
    const float* gamma   = (const float*)d_in[9];
    const float* beta    = (const float*)d_in[10];
    float* out = (float*)d_out;

    float* S = nullptr;
    float* stats = nullptr;
    cudaGetSymbolAddress((void**)&S, d_scratch);
    cudaGetSymbolAddress((void**)&stats, d_stats);

    float* theta   = S + OFF_THETA;
    float* gp      = S + OFF_G;
    float* php     = S + OFF_PHI;
    float* f       = S + OFF_F;
    float* y       = S + OFF_Y;
    float* wy      = S + OFF_WY;
    float* gfull   = S + OFF_F;               // alias: consumed before f is written
    float* phifull = S + OFF_F + OFF_G;       // alias (OFF_G == size of theta block? no —) 

    // NOTE: phifull must not overlap gfull; gfull is B*CI*NN = 12,845,056 floats.
    phifull = S + OFF_F + 12845056LL;

    const long long xStride = (long long)CC * NN;

    // 1) theta conv: (CI x N) = theta_w(CI x C) @ X(C x N), write transposed -> theta(b,n,ci)
    sgemm_kernel<0, 1><<<dim3(NN / 128, CI / 128, BB), 256>>>(
        theta_w, x, theta, theta_b, NN, CC, CC, NN, CI,
        0LL, xStride, (long long)NN * CI);

    // 2) g conv (full res) -> gfull(b,ci,n)
    sgemm_kernel<0, 0><<<dim3(NN / 128, CI / 128, BB), 256>>>(
        g_w, x, gfull, g_b, NN, CC, CC, NN, NN,
        0LL, xStride, (long long)CI * NN);

    // 3) phi conv (full res) -> phifull(b,ci,n)
    sgemm_kernel<0, 0><<<dim3(NN / 128, CI / 128, BB), 256>>>(
        phi_w, x, phifull, phi_b, NN, CC, CC, NN, NN,
        0LL, xStride, (long long)CI * NN);

    // 4) 2x2x2 maxpool + transpose -> g(b,m,ci), phi(b,m,ci)
    pool_kernel<<<dim3(BB * CI, TP), 196>>>(gfull, phifull, gp, php);

    // 5) f = theta @ phi^T : (N x M), K=CI   (overwrites the gfull/phifull alias region)
    sgemm_kernel<1, 0><<<dim3((MM + 127) / 128, NN / 128, BB), 256>>>(
        theta, php, f, nullptr, MM, CI, CI, CI, MM,
        (long long)NN * CI, (long long)MM * CI, (long long)NN * MM);

    // 6) softmax over last dim, in place
    softmax_kernel<<<BB * NN, 128>>>(f);

    // 7) y = f @ g : (N x CI), K=M
    sgemm_kernel<0, 0><<<dim3(CI / 128, NN / 128, BB), 256>>>(
        f, gp, y, nullptr, CI, MM, MM, CI, CI,
        (long long)NN * MM, (long long)MM * CI, (long long)NN * CI);

    // 8) wy = W_w @ y^T : (C x N), K=CI
    sgemm_kernel<1, 0><<<dim3(NN / 128, CC / 128, BB), 256>>>(
        W_w, y, wy, W_b, NN, CI, CI, CI, NN,
        0LL, (long long)NN * CI, (long long)CC * NN);

    // 9) BN batch stats per channel
    stats_kernel<<<CC, 256>>>(wy, stats);

    // 10) BN affine + residual
    const long long total4 = (long long)BB * CC * NN / 4;
    final_kernel<<<(unsigned)((total4 + 255) / 256), 256>>>(wy, x, gamma, beta, stats, out);
}